// round 14
// baseline (speedup 1.0000x reference)
#include <cuda_runtime.h>
#include <cuda_fp16.h>
#include <math.h>
#include <stdint.h>

#define EMB 1024
#define FF  4096
#define MTOK 8192

// ---------------- scratch (static device globals; no allocation) ----------------
__device__ __half g_w1q[FF * EMB];
__device__ __half g_w2q[EMB * FF];
__device__ __half g_xh[MTOK * EMB];
__device__ __half g_h[(size_t)MTOK * FF];
__device__ double g_part[2][512];

// ------- fused: absmean stage1 for both weights + x fp32->fp16 convert ---------
__global__ void prep_kernel(const float4* __restrict__ W1, const float4* __restrict__ W2,
                            int wn4, const float4* __restrict__ X, int xn4,
                            __half2* __restrict__ xo) {
    int b = blockIdx.x;
    int tid = threadIdx.x;
    if (b < 1024) {
        int which = b >> 9;
        int blk = b & 511;
        const float4* W = which ? W2 : W1;
        double s = 0.0;
        for (int i = blk * 256 + tid; i < wn4; i += 512 * 256) {
            float4 w = W[i];
            s += (double)((fabsf(w.x) + fabsf(w.y)) + (fabsf(w.z) + fabsf(w.w)));
        }
        __shared__ double sm[256];
        sm[tid] = s; __syncthreads();
        for (int o = 128; o > 0; o >>= 1) { if (tid < o) sm[tid] += sm[tid + o]; __syncthreads(); }
        if (tid == 0) g_part[which][blk] = sm[0];
    } else {
        int blk = b - 1024;                       // 1024 blocks for x convert
        for (int i = blk * 256 + tid; i < xn4; i += 1024 * 256) {
            float4 f = X[i];
            xo[2 * i]     = __halves2half2(__float2half_rn(f.x), __float2half_rn(f.y));
            xo[2 * i + 1] = __halves2half2(__float2half_rn(f.z), __float2half_rn(f.w));
        }
    }
}

// ---------------- ternarize both weights; scale reduced in-kernel --------------
__global__ void quantize_both(const float4* __restrict__ W1, const float4* __restrict__ W2,
                              int n4, __half2* __restrict__ o1, __half2* __restrict__ o2) {
    const int which = blockIdx.y;
    const float4* W = which ? W2 : W1;
    __half2* out = which ? o2 : o1;
    int tid = threadIdx.x;
    __shared__ double sm[256];
    __shared__ float ssc;
    sm[tid] = g_part[which][tid] + g_part[which][tid + 256];
    __syncthreads();
    for (int o = 128; o > 0; o >>= 1) { if (tid < o) sm[tid] += sm[tid + o]; __syncthreads(); }
    if (tid == 0) {
        float mean = (float)(sm[0] / (double)(n4 * 4));
        ssc = 1.0f / fmaxf(mean, 1e-8f);
    }
    __syncthreads();
    const float s = ssc;
    for (int i = blockIdx.x * blockDim.x + tid; i < n4; i += gridDim.x * blockDim.x) {
        float4 w = W[i];
        float q0 = fminf(1.0f, fmaxf(-1.0f, rintf(w.x * s)));
        float q1 = fminf(1.0f, fmaxf(-1.0f, rintf(w.y * s)));
        float q2 = fminf(1.0f, fmaxf(-1.0f, rintf(w.z * s)));
        float q3 = fminf(1.0f, fmaxf(-1.0f, rintf(w.w * s)));
        out[2 * i]     = __halves2half2(__float2half_rn(q0), __float2half_rn(q1));
        out[2 * i + 1] = __halves2half2(__float2half_rn(q2), __float2half_rn(q3));
    }
}

// ================= HMMA GEMM: C[M,N] = A[M,K] * B[N,K]^T =================
// 128 threads, 2x2 warps, warp tile (BM_/2 x BN_/2). KCH = K elems per stage row.
// KCH=64 -> 128B rows, swizzle c^(r&7). KCH=32 -> 64B rows, swizzle c^((r>>1)&3).

__device__ __forceinline__ void ldsm4(uint32_t& r0, uint32_t& r1, uint32_t& r2, uint32_t& r3,
                                      uint32_t a) {
    asm volatile("ldmatrix.sync.aligned.m8n8.x4.shared.b16 {%0,%1,%2,%3}, [%4];"
                 : "=r"(r0), "=r"(r1), "=r"(r2), "=r"(r3) : "r"(a));
}
__device__ __forceinline__ void mma16816(float* c, const uint32_t* a, const uint32_t* b) {
    asm volatile("mma.sync.aligned.m16n8k16.row.col.f32.f16.f16.f32 "
                 "{%0,%1,%2,%3}, {%4,%5,%6,%7}, {%8,%9}, {%0,%1,%2,%3};"
                 : "+f"(c[0]), "+f"(c[1]), "+f"(c[2]), "+f"(c[3])
                 : "r"(a[0]), "r"(a[1]), "r"(a[2]), "r"(a[3]), "r"(b[0]), "r"(b[1]));
}

// template-recursive cp.async with immediate offsets
template <int I, int N, int SSTR, int GSTR>
struct CpLoop {
    static __device__ __forceinline__ void run(uint32_t d, const char* s) {
        asm volatile("cp.async.cg.shared.global [%0+%2], [%1+%3], 16;\n"
                     :: "r"(d), "l"(s), "n"(I * SSTR), "n"(I * GSTR));
        CpLoop<I + 1, N, SSTR, GSTR>::run(d, s);
    }
};
template <int N, int SSTR, int GSTR>
struct CpLoop<N, N, SSTR, GSTR> {
    static __device__ __forceinline__ void run(uint32_t, const char*) {}
};

template <int BM_, int BN_, int KCH, int NS, int OCC, int N, int K, bool FUSE_GELU>
__global__ void __launch_bounds__(128, OCC)
ffn_gemm_h(const __half* __restrict__ A, const __half* __restrict__ B,
           const float* __restrict__ bias, __half* __restrict__ Oh,
           float* __restrict__ Of) {
    constexpr int MF = BM_ / 2 / 16;
    constexpr int NF = BN_ / 2 / 8;
    constexpr int RB = KCH * 2;                  // row bytes (128 or 64)
    constexpr int C  = RB / 16;                  // 16B chunks per row (8 or 4)
    constexpr int RPI = 128 / C;                 // rows per cp.async iter (16 or 32)
    constexpr uint32_t STAGE = (uint32_t)(BM_ + BN_) * RB;
    extern __shared__ char smem_raw[];
    const uint32_t sb = ((uint32_t)__cvta_generic_to_shared(smem_raw) + 127u) & ~127u;
    const int tid = threadIdx.x, lane = tid & 31, warp = tid >> 5;
    const int wm = (warp & 1) * (BM_ / 2);
    const int wn = (warp >> 1) * (BN_ / 2);
    const int bm = blockIdx.y * BM_, bn = blockIdx.x * BN_;

    // swizzle function: C==8 -> r&7 ; C==4 -> (r>>1)&3
    auto swz = [](int r) -> int { return (C == 8) ? (r & 7) : ((r >> 1) & 3); };

    const int chunk = tid & (C - 1);
    const int r0 = tid / C;                      // 0..RPI-1
    const uint32_t so0 = (uint32_t)(r0 * RB + ((chunk ^ swz(r0)) << 4));
    const char* gAp = (const char*)(A + (size_t)(bm + r0) * K) + chunk * 16;
    const char* gBp = (const char*)(B + (size_t)(bn + r0) * K) + chunk * 16;

    float c[MF][NF][4];
#pragma unroll
    for (int i = 0; i < MF; i++)
#pragma unroll
        for (int j = 0; j < NF; j++)
#pragma unroll
            for (int k = 0; k < 4; k++) c[i][j][k] = 0.0f;

    const int KT = K / KCH;
#pragma unroll
    for (int s = 0; s < NS - 1; s++) {
        CpLoop<0, BM_ / RPI, RPI * RB, RPI * K * 2>::run(sb + s * STAGE + so0, gAp + s * RB);
        CpLoop<0, BN_ / RPI, RPI * RB, RPI * K * 2>::run(sb + s * STAGE + BM_ * RB + so0,
                                                         gBp + s * RB);
        asm volatile("cp.async.commit_group;\n" ::: "memory");
    }
    gAp += (NS - 1) * RB;
    gBp += (NS - 1) * RB;

    // ---- precomputed ldmatrix offsets; ks enters via XOR (xk = ks<<5) ----
    const int lrow  = lane & 15;
    const int lhalf = lane >> 4;
    const int boff  = (lane >> 4) << 3;
    const int bkh   = (lane >> 3) & 1;
    uint32_t offA[MF], offB[NF / 2];
#pragma unroll
    for (int mi = 0; mi < MF; mi++) {
        int arow = wm + mi * 16 + lrow;
        offA[mi] = (uint32_t)(arow * RB + ((lhalf ^ swz(arow)) << 4));
    }
#pragma unroll
    for (int p = 0; p < NF / 2; p++) {
        int nrow = wn + p * 16 + boff + (lane & 7);
        offB[p] = (uint32_t)(BM_ * RB + nrow * RB + ((bkh ^ swz(nrow)) << 4));
    }

    uint32_t afr[MF][4], bfr[NF][2];

    for (int kt = 0; kt < KT; kt++) {
        asm volatile("cp.async.wait_group %0;\n" :: "n"(NS - 2) : "memory");
        __syncthreads();
        if (kt + NS - 1 < KT) {
            const uint32_t sd = sb + (uint32_t)((kt + NS - 1) % NS) * STAGE;
            CpLoop<0, BM_ / RPI, RPI * RB, RPI * K * 2>::run(sd + so0, gAp);
            CpLoop<0, BN_ / RPI, RPI * RB, RPI * K * 2>::run(sd + BM_ * RB + so0, gBp);
            asm volatile("cp.async.commit_group;\n" ::: "memory");
            gAp += RB; gBp += RB;
        } else {
            asm volatile("cp.async.commit_group;\n" ::: "memory");
        }

        const uint32_t aA = sb + (uint32_t)(kt % NS) * STAGE;

#pragma unroll
        for (int ks = 0; ks < KCH / 16; ks++) {
            const uint32_t xk = (uint32_t)(ks << 5);
#pragma unroll
            for (int p = 0; p < NF / 2; p++)
                ldsm4(bfr[2 * p][0], bfr[2 * p][1], bfr[2 * p + 1][0], bfr[2 * p + 1][1],
                      aA + (offB[p] ^ xk));
#pragma unroll
            for (int mi = 0; mi < MF; mi++)
                ldsm4(afr[mi][0], afr[mi][1], afr[mi][2], afr[mi][3],
                      aA + (offA[mi] ^ xk));
#pragma unroll
            for (int mi = 0; mi < MF; mi++)
#pragma unroll
                for (int ni = 0; ni < NF; ni++)
                    mma16816(c[mi][ni], afr[mi], bfr[ni]);
        }
    }

    // ---------------- epilogue ----------------
    const int g = lane >> 2, t = lane & 3;
#pragma unroll
    for (int mi = 0; mi < MF; mi++) {
#pragma unroll
        for (int ni = 0; ni < NF; ni++) {
            int m0 = bm + wm + mi * 16 + g;
            int n0 = bn + wn + ni * 8 + 2 * t;
            float bv0 = __ldg(bias + n0), bv1 = __ldg(bias + n0 + 1);
            float* cc = c[mi][ni];
#pragma unroll
            for (int half = 0; half < 2; half++) {
                int m = m0 + half * 8;
                float v0 = cc[2 * half + 0] + bv0;
                float v1 = cc[2 * half + 1] + bv1;
                if (FUSE_GELU) {
                    float gl0 = 0.5f * v0 * (1.0f + erff(v0 * 0.70710678118654752f));
                    float gl1 = 0.5f * v1 * (1.0f + erff(v1 * 0.70710678118654752f));
                    *(__half2*)(Oh + (size_t)m * N + n0) =
                        __halves2half2(__float2half_rn(gl0), __float2half_rn(gl1));
                } else {
                    float2 v; v.x = v0; v.y = v1;
                    *(float2*)(Of + (size_t)m * N + n0) = v;
                }
            }
        }
    }
}

// ---------------- launch ----------------
extern "C" void kernel_launch(void* const* d_in, const int* in_sizes, int n_in,
                              void* d_out, int out_size) {
    (void)in_sizes; (void)n_in; (void)out_size;
    const float* x  = (const float*)d_in[0];
    const float* W1 = (const float*)d_in[1];
    const float* b1 = (const float*)d_in[2];
    const float* W2 = (const float*)d_in[3];
    const float* b2 = (const float*)d_in[4];
    float* out = (float*)d_out;

    __half *w1q, *w2q, *xh, *h;
    cudaGetSymbolAddress((void**)&w1q, g_w1q);
    cudaGetSymbolAddress((void**)&w2q, g_w2q);
    cudaGetSymbolAddress((void**)&xh, g_xh);
    cudaGetSymbolAddress((void**)&h, g_h);

    prep_kernel<<<2048, 256>>>((const float4*)W1, (const float4*)W2, FF * EMB / 4,
                               (const float4*)x, MTOK * EMB / 4, (__half2*)xh);
    quantize_both<<<dim3(2048, 2), 256>>>((const float4*)W1, (const float4*)W2,
                                          FF * EMB / 4, (__half2*)w1q, (__half2*)w2q);

    // G1: 128x128, KCH=32 (64B rows), NS=4 (64KB) -> 3 CTAs/SM, 64x64 warp tiles.
    // G2: 64x128, KCH=64 (128B rows), NS=2 (48KB) -> 4 CTAs/SM (wave fix: 2.31->1.73 waves).
    constexpr int SMEM1 = 4 * (128 + 128) * 64 + 128;    // 65664
    constexpr int SMEM2 = 2 * (64 + 128) * 128 + 128;    // 49280
    cudaFuncSetAttribute(ffn_gemm_h<128, 128, 32, 4, 3, FF, EMB, true>,
                         cudaFuncAttributeMaxDynamicSharedMemorySize, SMEM1);
    cudaFuncSetAttribute(ffn_gemm_h<64, 128, 64, 2, 4, EMB, FF, false>,
                         cudaFuncAttributeMaxDynamicSharedMemorySize, SMEM2);

    ffn_gemm_h<128, 128, 32, 4, 3, FF, EMB, true><<<dim3(FF / 128, MTOK / 128), 128, SMEM1>>>(
        xh, w1q, b1, h, nullptr);
    ffn_gemm_h<64, 128, 64, 2, 4, EMB, FF, false><<<dim3(EMB / 128, MTOK / 64), 128, SMEM2>>>(
        h, w2q, b2, nullptr, out);
}

// round 16
// speedup vs baseline: 1.1012x; 1.1012x over previous
#include <cuda_runtime.h>
#include <cuda_fp16.h>
#include <math.h>
#include <stdint.h>

#define EMB 1024
#define FF  4096
#define MTOK 8192
#define PREP_BLOCKS 592

// ---------------- scratch (static device globals; no allocation) ----------------
__device__ __half g_w1q[FF * EMB];
__device__ __half g_w2q[EMB * FF];
__device__ __half g_xh[MTOK * EMB];
__device__ __half g_h[(size_t)MTOK * FF];
__device__ double g_part[2][256];
__device__ unsigned g_bar;

// ===== fused preprocessing: absmean + x-convert | global barrier | quantize =====
__global__ void __launch_bounds__(256, 4)
prep_all(const float4* __restrict__ W1, const float4* __restrict__ W2, int wn4,
         const float4* __restrict__ X, int xn4, __half2* __restrict__ xo,
         __half2* __restrict__ o1, __half2* __restrict__ o2) {
    const int b = blockIdx.x, tid = threadIdx.x;
    __shared__ double sm[256];
    __shared__ float ssc[2];

    // ---- phase 1a: x fp32 -> fp16 convert (all blocks, strided) ----
    for (int i = b * 256 + tid; i < xn4; i += PREP_BLOCKS * 256) {
        float4 f = X[i];
        xo[2 * i]     = __halves2half2(__float2half_rn(f.x), __float2half_rn(f.y));
        xo[2 * i + 1] = __halves2half2(__float2half_rn(f.z), __float2half_rn(f.w));
    }

    // ---- phase 1b: absmean partials (blocks 0..511; 256 partials per weight) ----
    if (b < 512) {
        const int which = b >> 8;
        const int blk = b & 255;
        const float4* W = which ? W2 : W1;
        double s = 0.0;
        for (int i = blk * 256 + tid; i < wn4; i += 256 * 256) {
            float4 w = W[i];
            s += (double)((fabsf(w.x) + fabsf(w.y)) + (fabsf(w.z) + fabsf(w.w)));
        }
        sm[tid] = s; __syncthreads();
        for (int o = 128; o > 0; o >>= 1) { if (tid < o) sm[tid] += sm[tid + o]; __syncthreads(); }
        if (tid == 0) g_part[which][blk] = sm[0];
    }

    // ---- global barrier (ticket/epoch; replay-safe, deterministic) ----
    __syncthreads();
    if (tid == 0) {
        __threadfence();
        unsigned ticket = atomicAdd(&g_bar, 1u);
        unsigned target = (ticket / PREP_BLOCKS + 1u) * PREP_BLOCKS;
        while (atomicAdd(&g_bar, 0u) < target) { }
        __threadfence();
    }
    __syncthreads();

    // ---- phase 2a: every block computes both scales (deterministic tree) ----
#pragma unroll
    for (int which = 0; which < 2; which++) {
        sm[tid] = g_part[which][tid];
        __syncthreads();
        for (int o = 128; o > 0; o >>= 1) { if (tid < o) sm[tid] += sm[tid + o]; __syncthreads(); }
        if (tid == 0) {
            float mean = (float)(sm[0] / (double)(wn4 * 4));
            ssc[which] = 1.0f / fmaxf(mean, 1e-8f);
        }
        __syncthreads();
    }
    const float s1 = ssc[0], s2 = ssc[1];

    // ---- phase 2b: ternarize both weights (strided over all blocks) ----
    for (int i = b * 256 + tid; i < wn4; i += PREP_BLOCKS * 256) {
        float4 w = W1[i];
        float q0 = fminf(1.0f, fmaxf(-1.0f, rintf(w.x * s1)));
        float q1 = fminf(1.0f, fmaxf(-1.0f, rintf(w.y * s1)));
        float q2 = fminf(1.0f, fmaxf(-1.0f, rintf(w.z * s1)));
        float q3 = fminf(1.0f, fmaxf(-1.0f, rintf(w.w * s1)));
        o1[2 * i]     = __halves2half2(__float2half_rn(q0), __float2half_rn(q1));
        o1[2 * i + 1] = __halves2half2(__float2half_rn(q2), __float2half_rn(q3));
    }
    for (int i = b * 256 + tid; i < wn4; i += PREP_BLOCKS * 256) {
        float4 w = W2[i];
        float q0 = fminf(1.0f, fmaxf(-1.0f, rintf(w.x * s2)));
        float q1 = fminf(1.0f, fmaxf(-1.0f, rintf(w.y * s2)));
        float q2 = fminf(1.0f, fmaxf(-1.0f, rintf(w.z * s2)));
        float q3 = fminf(1.0f, fmaxf(-1.0f, rintf(w.w * s2)));
        o2[2 * i]     = __halves2half2(__float2half_rn(q0), __float2half_rn(q1));
        o2[2 * i + 1] = __halves2half2(__float2half_rn(q2), __float2half_rn(q3));
    }
}

// ================= HMMA GEMM: C[M,N] = A[M,K] * B[N,K]^T =================
// Champion config: 64x128 CTA tile, 128 threads, 2x2 warps (warp tile 32x64),
// KCH=64 (128B rows), NS=3, 3 CTAs/SM.
#define BK 64

__device__ __forceinline__ void ldsm4(uint32_t& r0, uint32_t& r1, uint32_t& r2, uint32_t& r3,
                                      uint32_t a) {
    asm volatile("ldmatrix.sync.aligned.m8n8.x4.shared.b16 {%0,%1,%2,%3}, [%4];"
                 : "=r"(r0), "=r"(r1), "=r"(r2), "=r"(r3) : "r"(a));
}
__device__ __forceinline__ void mma16816(float* c, const uint32_t* a, const uint32_t* b) {
    asm volatile("mma.sync.aligned.m16n8k16.row.col.f32.f16.f16.f32 "
                 "{%0,%1,%2,%3}, {%4,%5,%6,%7}, {%8,%9}, {%0,%1,%2,%3};"
                 : "+f"(c[0]), "+f"(c[1]), "+f"(c[2]), "+f"(c[3])
                 : "r"(a[0]), "r"(a[1]), "r"(a[2]), "r"(a[3]), "r"(b[0]), "r"(b[1]));
}

// template-recursive cp.async with immediate offsets
template <int I, int N, int SSTR, int GSTR>
struct CpLoop {
    static __device__ __forceinline__ void run(uint32_t d, const char* s) {
        asm volatile("cp.async.cg.shared.global [%0+%2], [%1+%3], 16;\n"
                     :: "r"(d), "l"(s), "n"(I * SSTR), "n"(I * GSTR));
        CpLoop<I + 1, N, SSTR, GSTR>::run(d, s);
    }
};
template <int N, int SSTR, int GSTR>
struct CpLoop<N, N, SSTR, GSTR> {
    static __device__ __forceinline__ void run(uint32_t, const char*) {}
};

template <int BM_, int BN_, int NS, int OCC, int N, int K, bool FUSE_GELU>
__global__ void __launch_bounds__(128, OCC)
ffn_gemm_h(const __half* __restrict__ A, const __half* __restrict__ B,
           const float* __restrict__ bias, __half* __restrict__ Oh,
           float* __restrict__ Of) {
    constexpr int MF = BM_ / 2 / 16;
    constexpr int NF = BN_ / 2 / 8;
    constexpr uint32_t STAGE = (BM_ + BN_) * 128u;
    extern __shared__ char smem_raw[];
    const uint32_t sb = ((uint32_t)__cvta_generic_to_shared(smem_raw) + 127u) & ~127u;
    const int tid = threadIdx.x, lane = tid & 31, warp = tid >> 5;
    const int wm = (warp & 1) * (BM_ / 2);
    const int wn = (warp >> 1) * (BN_ / 2);
    const int bm = blockIdx.y * BM_, bn = blockIdx.x * BN_;

    const int chunk = tid & 7;
    const int r0 = tid >> 3;
    const uint32_t so0 = (uint32_t)(r0 * 128 + ((chunk ^ (r0 & 7)) << 4));
    const char* gAp = (const char*)(A + (size_t)(bm + r0) * K + chunk * 8);
    const char* gBp = (const char*)(B + (size_t)(bn + r0) * K + chunk * 8);

    float c[MF][NF][4];
#pragma unroll
    for (int i = 0; i < MF; i++)
#pragma unroll
        for (int j = 0; j < NF; j++)
#pragma unroll
            for (int k = 0; k < 4; k++) c[i][j][k] = 0.0f;

    const int KT = K / BK;
#pragma unroll
    for (int s = 0; s < NS - 1; s++) {
        CpLoop<0, BM_ / 16, 16 * 128, 16 * K * 2>::run(sb + s * STAGE + so0, gAp + s * 128);
        CpLoop<0, BN_ / 16, 16 * 128, 16 * K * 2>::run(sb + s * STAGE + BM_ * 128 + so0,
                                                       gBp + s * 128);
        asm volatile("cp.async.commit_group;\n" ::: "memory");
    }
    gAp += (NS - 1) * 128;
    gBp += (NS - 1) * 128;

    const int lrow  = lane & 15;
    const int lhalf = lane >> 4;
    const int boff  = (lane >> 4) << 3;
    const int bkh   = (lane >> 3) & 1;
    uint32_t offA[MF], offB[NF / 2];
#pragma unroll
    for (int mi = 0; mi < MF; mi++) {
        int arow = wm + mi * 16 + lrow;
        offA[mi] = (uint32_t)(arow * 128 + ((lhalf ^ (arow & 7)) << 4));
    }
#pragma unroll
    for (int p = 0; p < NF / 2; p++) {
        int nrow = wn + p * 16 + boff + (lane & 7);
        offB[p] = (uint32_t)(BM_ * 128 + nrow * 128 + ((bkh ^ (nrow & 7)) << 4));
    }

    uint32_t afr[MF][4], bfr[NF][2];

    for (int kt = 0; kt < KT; kt++) {
        asm volatile("cp.async.wait_group %0;\n" :: "n"(NS - 2) : "memory");
        __syncthreads();
        if (kt + NS - 1 < KT) {
            const uint32_t sd = sb + (uint32_t)((kt + NS - 1) % NS) * STAGE;
            CpLoop<0, BM_ / 16, 16 * 128, 16 * K * 2>::run(sd + so0, gAp);
            CpLoop<0, BN_ / 16, 16 * 128, 16 * K * 2>::run(sd + BM_ * 128 + so0, gBp);
            asm volatile("cp.async.commit_group;\n" ::: "memory");
            gAp += 128; gBp += 128;
        } else {
            asm volatile("cp.async.commit_group;\n" ::: "memory");
        }

        const uint32_t aA = sb + (uint32_t)(kt % NS) * STAGE;

#pragma unroll
        for (int ks = 0; ks < BK / 16; ks++) {
            const uint32_t xk = (uint32_t)(ks << 5);
            // aA has bits 0-6 clear -> (aA + off) ^ xk == aA + (off ^ xk)
#pragma unroll
            for (int p = 0; p < NF / 2; p++)
                ldsm4(bfr[2 * p][0], bfr[2 * p][1], bfr[2 * p + 1][0], bfr[2 * p + 1][1],
                      aA + (offB[p] ^ xk));
#pragma unroll
            for (int mi = 0; mi < MF; mi++)
                ldsm4(afr[mi][0], afr[mi][1], afr[mi][2], afr[mi][3],
                      aA + (offA[mi] ^ xk));
#pragma unroll
            for (int mi = 0; mi < MF; mi++)
#pragma unroll
                for (int ni = 0; ni < NF; ni++)
                    mma16816(c[mi][ni], afr[mi], bfr[ni]);
        }
    }

    // ---------------- epilogue ----------------
    const int g = lane >> 2, t = lane & 3;
#pragma unroll
    for (int mi = 0; mi < MF; mi++) {
#pragma unroll
        for (int ni = 0; ni < NF; ni++) {
            int m0 = bm + wm + mi * 16 + g;
            int n0 = bn + wn + ni * 8 + 2 * t;
            float bv0 = __ldg(bias + n0), bv1 = __ldg(bias + n0 + 1);
            float* cc = c[mi][ni];
#pragma unroll
            for (int half = 0; half < 2; half++) {
                int m = m0 + half * 8;
                float v0 = cc[2 * half + 0] + bv0;
                float v1 = cc[2 * half + 1] + bv1;
                if (FUSE_GELU) {
                    float gl0 = 0.5f * v0 * (1.0f + erff(v0 * 0.70710678118654752f));
                    float gl1 = 0.5f * v1 * (1.0f + erff(v1 * 0.70710678118654752f));
                    *(__half2*)(Oh + (size_t)m * N + n0) =
                        __halves2half2(__float2half_rn(gl0), __float2half_rn(gl1));
                } else {
                    float2 v; v.x = v0; v.y = v1;
                    *(float2*)(Of + (size_t)m * N + n0) = v;
                }
            }
        }
    }
}

// ---------------- launch ----------------
extern "C" void kernel_launch(void* const* d_in, const int* in_sizes, int n_in,
                              void* d_out, int out_size) {
    (void)in_sizes; (void)n_in; (void)out_size;
    const float* x  = (const float*)d_in[0];
    const float* W1 = (const float*)d_in[1];
    const float* b1 = (const float*)d_in[2];
    const float* W2 = (const float*)d_in[3];
    const float* b2 = (const float*)d_in[4];
    float* out = (float*)d_out;

    __half *w1q, *w2q, *xh, *h;
    cudaGetSymbolAddress((void**)&w1q, g_w1q);
    cudaGetSymbolAddress((void**)&w2q, g_w2q);
    cudaGetSymbolAddress((void**)&xh, g_xh);
    cudaGetSymbolAddress((void**)&h, g_h);

    prep_all<<<PREP_BLOCKS, 256>>>((const float4*)W1, (const float4*)W2, FF * EMB / 4,
                                   (const float4*)x, MTOK * EMB / 4, (__half2*)xh,
                                   (__half2*)w1q, (__half2*)w2q);

    // Both GEMMs: champion 64x128, NS=3, 3 CTAs/SM.
    constexpr int SMEM = 3 * (64 + 128) * 128 + 128;
    cudaFuncSetAttribute(ffn_gemm_h<64, 128, 3, 3, FF, EMB, true>,
                         cudaFuncAttributeMaxDynamicSharedMemorySize, SMEM);
    cudaFuncSetAttribute(ffn_gemm_h<64, 128, 3, 3, EMB, FF, false>,
                         cudaFuncAttributeMaxDynamicSharedMemorySize, SMEM);

    ffn_gemm_h<64, 128, 3, 3, FF, EMB, true><<<dim3(FF / 128, MTOK / 64), 128, SMEM>>>(
        xh, w1q, b1, h, nullptr);
    ffn_gemm_h<64, 128, 3, 3, EMB, FF, false><<<dim3(EMB / 128, MTOK / 64), 128, SMEM>>>(
        h, w2q, b2, nullptr, out);
}